// round 2
// baseline (speedup 1.0000x reference)
#include <cuda_runtime.h>
#include <stdint.h>

#define NP    4096
#define DF    256
#define TOPK  100
#define NBINS 4096
#define CAP   65536

// ---- scratch (static device globals; no allocation in kernel_launch) ----
__device__ float        g_c1[NP * DF];
__device__ float        g_c2[NP * DF];
__device__ float        g_sq1[NP];
__device__ float        g_sq2[NP];
__device__ float        g_d2[(size_t)NP * NP];   // 64 MB of squared distances
__device__ unsigned int g_hist[NBINS];
__device__ int          g_threshBin;
__device__ int          g_candCount;
__device__ float        g_cand[CAP];

// ---- reset counters/histogram (graph replays must be deterministic) ----
__global__ void k_init() {
    int i = blockIdx.x * blockDim.x + threadIdx.x;
    if (i < NBINS) g_hist[i] = 0u;
    if (i == 0) g_candCount = 0;
}

// ---- gather picked rows + squared norms (ids are int32: JAX demotes int64) ----
__global__ void k_gather(const float* __restrict__ fm,
                         const int* __restrict__ ids1,
                         const int* __restrict__ ids2) {
    int row = blockIdx.x;
    const int* ids = blockIdx.y ? ids2 : ids1;
    float* C  = blockIdx.y ? g_c2 : g_c1;
    float* SQ = blockIdx.y ? g_sq2 : g_sq1;

    int id = ids[row];
    const float4* src = (const float4*)(fm + (size_t)id * DF);
    float4 v = src[threadIdx.x];                       // 64 threads * 4 = 256 floats
    ((float4*)(C + (size_t)row * DF))[threadIdx.x] = v;

    float s = v.x * v.x + v.y * v.y + v.z * v.z + v.w * v.w;
    #pragma unroll
    for (int o = 16; o; o >>= 1) s += __shfl_down_sync(0xffffffffu, s, o);

    __shared__ float ws[2];
    if ((threadIdx.x & 31) == 0) ws[threadIdx.x >> 5] = s;
    __syncthreads();
    if (threadIdx.x == 0) SQ[row] = ws[0] + ws[1];
}

// ---- 128x128 tile of squared distances + shared-mem histogram ----
__global__ __launch_bounds__(256) void k_dist() {
    __shared__ float As[32][129];
    __shared__ float Bs[32][129];

    const int t  = threadIdx.x;
    const int p0 = blockIdx.y * 128;
    const int q0 = blockIdx.x * 128;
    const int lr = t >> 3;      // 0..31
    const int lc = t & 7;       // 0..7 (float4 column)

    float acc[8][8];
    #pragma unroll
    for (int i = 0; i < 8; i++)
        #pragma unroll
        for (int j = 0; j < 8; j++) acc[i][j] = 0.f;

    const int ty = t >> 4, tx = t & 15;

    for (int k0 = 0; k0 < DF; k0 += 32) {
        #pragma unroll
        for (int i = 0; i < 4; i++) {
            int r = lr + 32 * i;
            float4 a = *(const float4*)&g_c1[(size_t)(p0 + r) * DF + k0 + lc * 4];
            float4 b = *(const float4*)&g_c2[(size_t)(q0 + r) * DF + k0 + lc * 4];
            As[lc * 4 + 0][r] = a.x; As[lc * 4 + 1][r] = a.y;
            As[lc * 4 + 2][r] = a.z; As[lc * 4 + 3][r] = a.w;
            Bs[lc * 4 + 0][r] = b.x; Bs[lc * 4 + 1][r] = b.y;
            Bs[lc * 4 + 2][r] = b.z; Bs[lc * 4 + 3][r] = b.w;
        }
        __syncthreads();

        #pragma unroll
        for (int kk = 0; kk < 32; kk++) {
            float a[8], b[8];
            #pragma unroll
            for (int i = 0; i < 8; i++) a[i] = As[kk][ty * 8 + i];
            #pragma unroll
            for (int j = 0; j < 8; j++) b[j] = Bs[kk][tx * 8 + j];
            #pragma unroll
            for (int i = 0; i < 8; i++)
                #pragma unroll
                for (int j = 0; j < 8; j++) acc[i][j] += a[i] * b[j];
        }
        __syncthreads();
    }

    // Tiles are dead now; reuse As storage as the per-block histogram (16 KB).
    unsigned int* hist = (unsigned int*)&As[0][0];
    for (int i = t; i < NBINS; i += 256) hist[i] = 0u;
    __syncthreads();

    float sp[8], sq[8];
    #pragma unroll
    for (int i = 0; i < 8; i++) sp[i] = g_sq1[p0 + ty * 8 + i];
    #pragma unroll
    for (int j = 0; j < 8; j++) sq[j] = g_sq2[q0 + tx * 8 + j];

    #pragma unroll
    for (int i = 0; i < 8; i++) {
        float o[8];
        #pragma unroll
        for (int j = 0; j < 8; j++) {
            float d2 = fmaxf(sp[i] + sq[j] - 2.f * acc[i][j], 0.f);
            o[j] = d2;
            unsigned bin = __float_as_uint(d2) >> 20;   // monotonic for d2 >= 0
            if (bin >= NBINS) bin = NBINS - 1;
            atomicAdd(&hist[bin], 1u);
        }
        float4* dst = (float4*)&g_d2[(size_t)(p0 + ty * 8 + i) * NP + q0 + tx * 8];
        dst[0] = *(float4*)&o[0];
        dst[1] = *(float4*)&o[4];
    }
    __syncthreads();

    for (int i = t; i < NBINS; i += 256) {
        unsigned h = hist[i];
        if (h) atomicAdd(&g_hist[i], h);
    }
}

// ---- find the histogram bin containing the rank-TOPK value ----
__global__ void k_thresh() {
    unsigned long long cum = 0;
    for (int b = NBINS - 1; b >= 0; b--) {
        cum += g_hist[b];
        if (cum >= TOPK) { g_threshBin = b; return; }
    }
    g_threshBin = 0;
}

// ---- compact all values whose bin >= threshold ----
__global__ void k_compact() {
    size_t i = (size_t)blockIdx.x * blockDim.x + threadIdx.x;
    const float4 v = ((const float4*)g_d2)[i];
    const unsigned tb = (unsigned)g_threshBin;
    float x[4] = {v.x, v.y, v.z, v.w};
    #pragma unroll
    for (int j = 0; j < 4; j++) {
        if ((__float_as_uint(x[j]) >> 20) >= tb) {
            int p = atomicAdd(&g_candCount, 1);
            if (p < CAP) g_cand[p] = x[j];
        }
    }
}

// ---- exact top-100 over candidates (global scan, single block), mean of sqrt ----
__global__ __launch_bounds__(1024) void k_select(float* __restrict__ out) {
    __shared__ float red[1024];
    __shared__ int   redi[1024];
    __shared__ float s_sum;

    const int t = threadIdx.x;
    int n = g_candCount;
    if (n > CAP) n = CAP;
    if (t == 0) s_sum = 0.f;
    __syncthreads();

    for (int it = 0; it < TOPK; it++) {
        float m = -1.f; int mi = -1;
        for (int i = t; i < n; i += 1024) {
            float v = g_cand[i];
            if (v > m) { m = v; mi = i; }
        }
        red[t] = m; redi[t] = mi;
        __syncthreads();
        #pragma unroll
        for (int s = 512; s > 0; s >>= 1) {
            if (t < s) {
                if (red[t + s] > red[t]) { red[t] = red[t + s]; redi[t] = redi[t + s]; }
            }
            __syncthreads();
        }
        if (t == 0) {
            if (redi[0] >= 0) {
                s_sum += sqrtf(red[0]);     // descending order -> deterministic sum
                g_cand[redi[0]] = -1.f;
            }
        }
        __syncthreads();   // also orders the global write for next iteration
    }
    if (t == 0) *out = s_sum / (float)TOPK;
}

extern "C" void kernel_launch(void* const* d_in, const int* in_sizes, int n_in,
                              void* d_out, int out_size) {
    const float* fm   = (const float*)d_in[0];
    const int*   ids1 = (const int*)d_in[1];
    const int*   ids2 = (const int*)d_in[2];
    float* out = (float*)d_out;

    k_init<<<(NBINS + 255) / 256, 256>>>();
    k_gather<<<dim3(NP, 2), 64>>>(fm, ids1, ids2);
    k_dist<<<dim3(NP / 128, NP / 128), 256>>>();
    k_thresh<<<1, 1>>>();
    k_compact<<<(NP * NP / 4) / 256, 256>>>();
    k_select<<<1, 1024>>>(out);
}

// round 5
// speedup vs baseline: 2.5458x; 2.5458x over previous
#include <cuda_runtime.h>
#include <cuda_bf16.h>
#include <stdint.h>

#define NP    4096
#define DF    256
#define TOPK  100
#define NBINS 4096
#define CAP   65536

// ---- scratch (static device globals; no allocation in kernel_launch) ----
__device__ __nv_bfloat16 g_c1b[NP * DF];
__device__ __nv_bfloat16 g_c2b[NP * DF];
__device__ float         g_sq1[NP];
__device__ float         g_sq2[NP];
__device__ float         g_d2[(size_t)NP * NP];   // 64 MB squared distances
__device__ unsigned int  g_hist[NBINS];
__device__ int           g_threshBin;
__device__ int           g_candCount;
__device__ float         g_cand[CAP];

__device__ __forceinline__ uint32_t smem_u32(const void* p) {
    uint32_t a;
    asm("{ .reg .u64 t; cvta.to.shared.u64 t, %1; cvt.u32.u64 %0, t; }" : "=r"(a) : "l"(p));
    return a;
}

#define LDSM_X4(r0, r1, r2, r3, addr)                                          \
    asm volatile("ldmatrix.sync.aligned.m8n8.x4.shared.b16 {%0,%1,%2,%3}, [%4];" \
        : "=r"(r0), "=r"(r1), "=r"(r2), "=r"(r3) : "r"(addr))

#define MMA16816(c, a0, a1, a2, a3, b0, b1)                                    \
    asm volatile("mma.sync.aligned.m16n8k16.row.col.f32.bf16.bf16.f32 "        \
        "{%0,%1,%2,%3}, {%4,%5,%6,%7}, {%8,%9}, {%0,%1,%2,%3};"                \
        : "+f"((c)[0]), "+f"((c)[1]), "+f"((c)[2]), "+f"((c)[3])               \
        : "r"(a0), "r"(a1), "r"(a2), "r"(a3), "r"(b0), "r"(b1))

// ---- dynamic SMEM layout for k_dist (bytes) ----
// padded bf16 tiles: 128 rows x 264 elems (528 B row) -> conflict-free ldmatrix
#define PADROW  264
#define SM_HIST 0                         // 4096 x u32 = 16384
#define SM_SP   16384                     // 128 f32
#define SM_SQ   16896                     // 128 f32
#define SM_A    17408                     // 128*528 = 67584
#define SM_B    (SM_A + 128 * PADROW * 2)
#define SM_TOT  (SM_B + 128 * PADROW * 2) // 152576

// ================= kernels =================

__global__ void k_init() {
    int i = blockIdx.x * blockDim.x + threadIdx.x;
    if (i < NBINS) g_hist[i] = 0u;
    if (i == 0) g_candCount = 0;
}

// gather picked rows (-> bf16 copies) + exact fp32 squared norms
__global__ void k_gather(const float* __restrict__ fm,
                         const int* __restrict__ ids1,
                         const int* __restrict__ ids2) {
    int row = blockIdx.x;
    const int* ids = blockIdx.y ? ids2 : ids1;
    __nv_bfloat16* C = blockIdx.y ? g_c2b : g_c1b;
    float*        SQ = blockIdx.y ? g_sq2 : g_sq1;

    int id = ids[row];
    float4 v = ((const float4*)(fm + (size_t)id * DF))[threadIdx.x];  // 64 thr * 4

    unsigned lo = ((unsigned)__bfloat16_as_ushort(__float2bfloat16(v.y)) << 16) |
                   (unsigned)__bfloat16_as_ushort(__float2bfloat16(v.x));
    unsigned hi = ((unsigned)__bfloat16_as_ushort(__float2bfloat16(v.w)) << 16) |
                   (unsigned)__bfloat16_as_ushort(__float2bfloat16(v.z));
    *(uint2*)&C[(size_t)row * DF + threadIdx.x * 4] = make_uint2(lo, hi);

    float s = v.x * v.x + v.y * v.y + v.z * v.z + v.w * v.w;
    #pragma unroll
    for (int o = 16; o; o >>= 1) s += __shfl_down_sync(0xffffffffu, s, o);
    __shared__ float ws[2];
    if ((threadIdx.x & 31) == 0) ws[threadIdx.x >> 5] = s;
    __syncthreads();
    if (threadIdx.x == 0) SQ[row] = ws[0] + ws[1];
}

// 128x128 tile of squared distances via bf16 mma.sync + smem histogram
__global__ __launch_bounds__(256, 1) void k_dist() {
    extern __shared__ char sm[];
    const uint32_t sb = smem_u32(sm);
    const int t = threadIdx.x, lane = t & 31, w = t >> 5;
    const int p0 = blockIdx.y * 128, q0 = blockIdx.x * 128;

    unsigned* hist = (unsigned*)(sm + SM_HIST);
    for (int i = t; i < NBINS; i += 256) hist[i] = 0u;
    if (t < 128)       ((float*)(sm + SM_SP))[t]       = g_sq1[p0 + t];
    else               ((float*)(sm + SM_SQ))[t - 128] = g_sq2[q0 + t - 128];

    // stage both 128x256 bf16 tiles (padded rows of 264)
    #pragma unroll
    for (int i = 0; i < 16; i++) {
        int idx = i * 256 + t;
        int r = idx >> 5, c = idx & 31;                     // c: 16B chunk
        uint4 va = *(const uint4*)&g_c1b[(size_t)(p0 + r) * DF + c * 8];
        uint4 vb = *(const uint4*)&g_c2b[(size_t)(q0 + r) * DF + c * 8];
        *(uint4*)(sm + SM_A + r * (PADROW * 2) + c * 16) = va;
        *(uint4*)(sm + SM_B + r * (PADROW * 2) + c * 16) = vb;
    }
    __syncthreads();

    // warp layout: 4 warps along M (32 rows each), 2 along N (64 cols each)
    const int mbase = (w & 3) * 32;
    const int nbase = (w >> 2) * 64;

    // ldmatrix base addresses (k-offset added per step)
    uint32_t aAddr[2], bAddr[4];
    #pragma unroll
    for (int i = 0; i < 2; i++) {
        int row = mbase + i * 16 + (lane & 15);
        aAddr[i] = sb + SM_A + row * (PADROW * 2) + (lane >> 4) * 16;
    }
    #pragma unroll
    for (int jp = 0; jp < 4; jp++) {
        int row = nbase + jp * 16 + (lane & 7) + ((lane >> 4) & 1) * 8;
        bAddr[jp] = sb + SM_B + row * (PADROW * 2) + ((lane >> 3) & 1) * 16;
    }

    float c[2][8][4];
    #pragma unroll
    for (int i = 0; i < 2; i++)
        #pragma unroll
        for (int j = 0; j < 8; j++)
            #pragma unroll
            for (int r = 0; r < 4; r++) c[i][j][r] = 0.f;

    #pragma unroll
    for (int ks = 0; ks < 16; ks++) {           // K = 16 steps of 16
        const uint32_t ko = ks * 32;            // 16 bf16 = 32 B
        uint32_t a[2][4], b[8][2];
        #pragma unroll
        for (int i = 0; i < 2; i++)
            LDSM_X4(a[i][0], a[i][1], a[i][2], a[i][3], aAddr[i] + ko);
        #pragma unroll
        for (int jp = 0; jp < 4; jp++)
            LDSM_X4(b[2 * jp][0], b[2 * jp][1], b[2 * jp + 1][0], b[2 * jp + 1][1],
                    bAddr[jp] + ko);
        #pragma unroll
        for (int i = 0; i < 2; i++)
            #pragma unroll
            for (int j = 0; j < 8; j++)
                MMA16816(c[i][j], a[i][0], a[i][1], a[i][2], a[i][3], b[j][0], b[j][1]);
    }

    // epilogue: d2 = sp + sq - 2*dot, histogram, store
    const float* sps = (const float*)(sm + SM_SP);
    const float* sqs = (const float*)(sm + SM_SQ);
    #pragma unroll
    for (int i = 0; i < 2; i++) {
        const int r0 = mbase + i * 16 + (lane >> 2);     // local row (c0,c1)
        const float sp0 = sps[r0], sp1 = sps[r0 + 8];
        #pragma unroll
        for (int j = 0; j < 8; j++) {
            const int cl = nbase + j * 8 + (lane & 3) * 2;  // local col
            const float sq0 = sqs[cl], sq1 = sqs[cl + 1];
            float d0 = fmaxf(sp0 + sq0 - 2.f * c[i][j][0], 0.f);
            float d1 = fmaxf(sp0 + sq1 - 2.f * c[i][j][1], 0.f);
            float d2v = fmaxf(sp1 + sq0 - 2.f * c[i][j][2], 0.f);
            float d3 = fmaxf(sp1 + sq1 - 2.f * c[i][j][3], 0.f);
            unsigned b0 = __float_as_uint(d0) >> 20; if (b0 >= NBINS) b0 = NBINS - 1;
            unsigned b1 = __float_as_uint(d1) >> 20; if (b1 >= NBINS) b1 = NBINS - 1;
            unsigned b2 = __float_as_uint(d2v) >> 20; if (b2 >= NBINS) b2 = NBINS - 1;
            unsigned b3 = __float_as_uint(d3) >> 20; if (b3 >= NBINS) b3 = NBINS - 1;
            atomicAdd(&hist[b0], 1u); atomicAdd(&hist[b1], 1u);
            atomicAdd(&hist[b2], 1u); atomicAdd(&hist[b3], 1u);
            *(float2*)&g_d2[(size_t)(p0 + r0)     * NP + q0 + cl] = make_float2(d0, d1);
            *(float2*)&g_d2[(size_t)(p0 + r0 + 8) * NP + q0 + cl] = make_float2(d2v, d3);
        }
    }
    __syncthreads();
    for (int i = t; i < NBINS; i += 256) {
        unsigned h = hist[i];
        if (h) atomicAdd(&g_hist[i], h);
    }
}

// parallel suffix-scan threshold: bin containing the rank-TOPK value
__global__ __launch_bounds__(1024) void k_thresh() {
    __shared__ unsigned scan[1024];
    const int t = threadIdx.x;
    const int btop = NBINS - 1 - 4 * t;          // group t: 4 bins descending
    unsigned h0 = g_hist[btop], h1 = g_hist[btop - 1],
             h2 = g_hist[btop - 2], h3 = g_hist[btop - 3];
    unsigned p = h0 + h1 + h2 + h3;
    scan[t] = p;
    __syncthreads();
    #pragma unroll
    for (int o = 1; o < 1024; o <<= 1) {
        unsigned v = (t >= o) ? scan[t - o] : 0u;
        __syncthreads();
        if (t >= o) scan[t] += v;
        __syncthreads();
    }
    unsigned excl = scan[t] - p;                 // count in all higher bins
    if (excl < TOPK && excl + p >= TOPK) {       // exactly one thread crosses
        unsigned cum = excl;
        int b = btop;
        cum += h0; if (cum >= TOPK) { g_threshBin = b; return; } b--;
        cum += h1; if (cum >= TOPK) { g_threshBin = b; return; } b--;
        cum += h2; if (cum >= TOPK) { g_threshBin = b; return; } b--;
        g_threshBin = b;
    }
}

// compact all values whose bin >= threshold
__global__ void k_compact() {
    size_t i = (size_t)blockIdx.x * blockDim.x + threadIdx.x;
    const float4 v = ((const float4*)g_d2)[i];
    const unsigned tb = (unsigned)g_threshBin;
    float x[4] = {v.x, v.y, v.z, v.w};
    #pragma unroll
    for (int j = 0; j < 4; j++) {
        if ((__float_as_uint(x[j]) >> 20) >= tb) {
            int p = atomicAdd(&g_candCount, 1);
            if (p < CAP) g_cand[p] = x[j];
        }
    }
}

// exact top-100 over candidates, mean of sqrt (descending -> deterministic)
__global__ __launch_bounds__(1024) void k_select(float* __restrict__ out) {
    __shared__ float red[1024];
    __shared__ int   redi[1024];
    __shared__ float s_sum;
    const int t = threadIdx.x;
    int n = g_candCount;
    if (n > CAP) n = CAP;
    if (t == 0) s_sum = 0.f;
    __syncthreads();

    for (int it = 0; it < TOPK; it++) {
        float m = -1.f; int mi = -1;
        for (int i = t; i < n; i += 1024) {
            float v = g_cand[i];
            if (v > m) { m = v; mi = i; }
        }
        red[t] = m; redi[t] = mi;
        __syncthreads();
        #pragma unroll
        for (int s = 512; s > 0; s >>= 1) {
            if (t < s && red[t + s] > red[t]) { red[t] = red[t + s]; redi[t] = redi[t + s]; }
            __syncthreads();
        }
        if (t == 0 && redi[0] >= 0) {
            s_sum += sqrtf(red[0]);
            g_cand[redi[0]] = -1.f;
        }
        __syncthreads();
    }
    if (t == 0) *out = s_sum / (float)TOPK;
}

extern "C" void kernel_launch(void* const* d_in, const int* in_sizes, int n_in,
                              void* d_out, int out_size) {
    const float* fm   = (const float*)d_in[0];
    const int*   ids1 = (const int*)d_in[1];
    const int*   ids2 = (const int*)d_in[2];
    float* out = (float*)d_out;

    static int smem_set = 0;
    if (!smem_set) {
        cudaFuncSetAttribute(k_dist, cudaFuncAttributeMaxDynamicSharedMemorySize, SM_TOT);
        smem_set = 1;
    }

    k_init<<<(NBINS + 255) / 256, 256>>>();
    k_gather<<<dim3(NP, 2), 64>>>(fm, ids1, ids2);
    k_dist<<<dim3(NP / 128, NP / 128), 256, SM_TOT>>>();
    k_thresh<<<1, 1024>>>();
    k_compact<<<(NP * NP / 4) / 256, 256>>>();
    k_select<<<1, 1024>>>(out);
}